// round 3
// baseline (speedup 1.0000x reference)
#include <cuda_runtime.h>

// ---------------- scratch (no allocations allowed) ----------------
#define NTOK (2*4096)              // 8192 tokens
__device__ float g_xt[NTOK*64];    // x in NHWC
__device__ float g_b1[NTOK*64];    // conv1 output (relu), NHWC
__device__ float g_t [NTOK*64];    // conv2 output (= h = t), NHWC
__device__ float g_wt1[64*9*64];   // conv1 weights [ci][k][co]
__device__ float g_wt2[64*9*64];   // conv2 weights [ci][k][co]

__device__ __forceinline__ float ex2f(float x) {
    float y; asm("ex2.approx.f32 %0, %1;" : "=f"(y) : "f"(x)); return y;
}

// ---------------- prep: NCHW -> NHWC transpose of x ----------------
__global__ void k_transpose_x(const float* __restrict__ x) {
    __shared__ float tile[32][33];
    int b  = blockIdx.z;
    int c0 = blockIdx.y * 32;
    int s0 = blockIdx.x * 32;
    int tx = threadIdx.x, ty = threadIdx.y;
#pragma unroll
    for (int i = 0; i < 32; i += 8)
        tile[ty + i][tx] = x[(b*64 + c0 + ty + i) * 4096 + s0 + tx];
    __syncthreads();
#pragma unroll
    for (int i = 0; i < 32; i += 8)
        g_xt[(b*4096 + s0 + ty + i) * 64 + c0 + tx] = tile[tx][ty + i];
}

// ---------------- prep: conv weights [co][ci][3][3] -> [ci][k][co] ----------------
__global__ void k_transpose_w(const float* __restrict__ w1, const float* __restrict__ w2) {
    int i = blockIdx.x * blockDim.x + threadIdx.x;
    if (i >= 2 * 36864) return;
    const float* w = (i < 36864) ? w1 : w2;
    float* dst     = (i < 36864) ? g_wt1 : g_wt2;
    int o  = (i < 36864) ? i : (i - 36864);
    int ci = o / 576;
    int k  = (o % 576) / 64;
    int co = o & 63;
    dst[o] = w[co * 576 + ci * 9 + k];
}

// ---------------- conv3x3 (NHWC in/out), 64->64 channels ----------------
// block: 256 threads = 64 co x 4 groups (row r_o in 0..1, half h in 0..1).
// tile: 2 rows x 8 px; 4 px per thread. grid (8,32,2) = 1024? no: (8,32,2)=512 blocks.
// double-buffered ci chunks of 8.
template<bool RELU, int SRC>
__global__ void __launch_bounds__(256) k_conv(const float* __restrict__ bias) {
    const float* __restrict__ in  = (SRC == 0) ? g_xt  : g_b1;
    const float* __restrict__ wt  = (SRC == 0) ? g_wt1 : g_wt2;
    float* __restrict__       out = (SRC == 0) ? g_b1  : g_t;

    __shared__ float w_s[2][4608];       // 8 ci x 9 k x 64 co
    __shared__ float in_s[2][8][48];     // [ci][row*12 + xx], row<4, xx<10 (pad 12)

    const int tid = threadIdx.x;
    const int co  = tid & 63;
    const int g   = tid >> 6;            // 0..3
    const int r_o = g >> 1;              // output row within tile (0..1)
    const int h   = g & 1;               // 4-px half (0..1)
    const int x0 = blockIdx.x * 8, y0 = blockIdx.y * 2, b = blockIdx.z;

    // staging thread mapping (inputs): 80 active threads x 4 rows
    const int s_ci = tid & 7;
    const int s_xx = tid >> 3;           // 0..31, active when <10
    const int s_xg = x0 - 1 + s_xx;
    const bool s_act = (s_xx < 10);

    float acc[4];
#pragma unroll
    for (int p = 0; p < 4; p++) acc[p] = 0.f;

    // stage chunk c (ci0 = 8c) into buffer bufi
    auto stage = [&](int c, int bufi) {
        const float2* wsrc = (const float2*)(wt + c * 4608);
        float2* wdst = (float2*)w_s[bufi];
#pragma unroll
        for (int i = 0; i < 9; i++)
            wdst[tid + i * 256] = wsrc[tid + i * 256];
        if (s_act) {
#pragma unroll
            for (int r = 0; r < 4; r++) {
                int y = y0 - 1 + r;
                float v = 0.f;
                if ((unsigned)y < 64u && (unsigned)s_xg < 64u)
                    v = in[((b * 64 + y) * 64 + s_xg) * 64 + c * 8 + s_ci];
                in_s[bufi][s_ci][r * 12 + s_xx] = v;
            }
        }
    };

    stage(0, 0);
    __syncthreads();

#pragma unroll
    for (int c = 0; c < 8; c++) {
        const int bufi = c & 1;
        if (c < 7) stage(c + 1, bufi ^ 1);

        const float* wb = w_s[bufi];
        const float* ib = &in_s[bufi][0][0];
#pragma unroll
        for (int ci = 0; ci < 8; ci++) {
            const float* wrow = wb + ci * 576 + co;
            float w[9];
#pragma unroll
            for (int k = 0; k < 9; k++) w[k] = wrow[k * 64];
            const float* irow = ib + ci * 48 + r_o * 12 + h * 4;
#pragma unroll
            for (int dy = 0; dy < 3; dy++) {
                float4 v0 = *(const float4*)(irow + dy * 12);
                float2 v1 = *(const float2*)(irow + dy * 12 + 4);
                float a[6] = {v0.x, v0.y, v0.z, v0.w, v1.x, v1.y};
#pragma unroll
                for (int p = 0; p < 4; p++)
                    acc[p] = fmaf(w[dy*3+0], a[p],
                             fmaf(w[dy*3+1], a[p + 1],
                             fmaf(w[dy*3+2], a[p + 2], acc[p])));
            }
        }
        __syncthreads();
    }

    float bv = bias[co];
    int y = y0 + r_o;
    int base = ((b * 64 + y) * 64 + x0 + h * 4) * 64 + co;
#pragma unroll
    for (int p = 0; p < 4; p++) {
        float o = acc[p] + bv;
        if (RELU) o = fmaxf(o, 0.f);
        out[base + p * 64] = o;          // lanes = co -> coalesced
    }
}

// ---------------- attention: 32 tokens per block, 256 threads ----------------
// out_c = sum_d exp(q_c k_d) v_d / sum_d exp(q_c k_d);  final = Wo out + bo + t
#define SMEM_FLOATS (4*4160 + 4*2080)   // 24960 floats = 99840 bytes
__global__ void __launch_bounds__(256) k_attn(
    const float* __restrict__ wq, const float* __restrict__ wk,
    const float* __restrict__ wv, const float* __restrict__ wo,
    const float* __restrict__ bo, float* __restrict__ out)
{
    extern __shared__ float sm[];
    float* wq_s = sm;                  // [l][c], row pad 65
    float* wk_s = sm + 4160;
    float* wv_s = sm + 8320;
    float* wo_s = sm + 12480;          // [c][c'], row pad 65
    float* t_s  = sm + 16640;          // [32][65]
    float* k_s  = t_s + 2080;
    float* v_s  = k_s + 2080;
    float* o_s  = v_s + 2080;

    int tid = threadIdx.x;
    int n0  = blockIdx.x * 32;

    // weights: read coalesced [c][l], write transposed (pad-65 kills bank conflicts)
#pragma unroll 4
    for (int i = 0; i < 16; i++) {
        int g = tid + i * 256;
        int c = g >> 6, l = g & 63;
        wq_s[l * 65 + c] = wq[g];
        wk_s[l * 65 + c] = wk[g];
        wv_s[l * 65 + c] = wv[g];
        wo_s[l * 65 + c] = wo[g];
    }
#pragma unroll
    for (int i = 0; i < 8; i++) {
        int g = tid + i * 256;
        t_s[(g >> 6) * 65 + (g & 63)] = g_t[n0 * 64 + g];
    }
    __syncthreads();

    // phase 1: q/k/v matvecs. thread = (token tt, 8-channel group c0)
    int tt = tid >> 3, cg = tid & 7, c0 = cg * 8;
    float q[8], kk[8], vv[8];
#pragma unroll
    for (int j = 0; j < 8; j++) { q[j] = 0.f; kk[j] = 0.f; vv[j] = 0.f; }
    const float* trow = t_s + tt * 65;
#pragma unroll 4
    for (int l = 0; l < 64; l++) {
        float tl = trow[l];
        const float* wql = wq_s + l * 65 + c0;
        const float* wkl = wk_s + l * 65 + c0;
        const float* wvl = wv_s + l * 65 + c0;
#pragma unroll
        for (int j = 0; j < 8; j++) {
            q[j]  = fmaf(tl, wql[j], q[j]);
            kk[j] = fmaf(tl, wkl[j], kk[j]);
            vv[j] = fmaf(tl, wvl[j], vv[j]);
        }
    }
    // L2 norms over the 8-lane token group
    float sq = 0.f, sk = 0.f;
#pragma unroll
    for (int j = 0; j < 8; j++) { sq = fmaf(q[j], q[j], sq); sk = fmaf(kk[j], kk[j], sk); }
#pragma unroll
    for (int off = 1; off < 8; off <<= 1) {
        sq += __shfl_xor_sync(0xffffffffu, sq, off);
        sk += __shfl_xor_sync(0xffffffffu, sk, off);
    }
    const float LOG2E = 1.4426950408889634f;
    float invq = LOG2E / fmaxf(sqrtf(sq), 1e-12f);   // fold log2(e) into q
    float invk = 1.0f  / fmaxf(sqrtf(sk), 1e-12f);
#pragma unroll
    for (int j = 0; j < 8; j++) {
        q[j] *= invq;
        k_s[tt * 65 + c0 + j] = kk[j] * invk;
        v_s[tt * 65 + c0 + j] = vv[j];
    }
    __syncthreads();

    // phase 2: rank-1 softmax-attention, 2^(qs_c * k_d)
    float num[8], den[8];
#pragma unroll
    for (int j = 0; j < 8; j++) { num[j] = 0.f; den[j] = 0.f; }
    const float* krow = k_s + tt * 65;
    const float* vrow = v_s + tt * 65;
#pragma unroll 2
    for (int d = 0; d < 64; d++) {
        float kd = krow[d];
        float vd = vrow[d];
#pragma unroll
        for (int j = 0; j < 8; j++) {
            float e = ex2f(q[j] * kd);
            num[j] = fmaf(e, vd, num[j]);
            den[j] += e;
        }
    }
#pragma unroll
    for (int j = 0; j < 8; j++)
        o_s[tt * 65 + c0 + j] = __fdividef(num[j], den[j]);
    __syncthreads();

    // phase 3: out-projection + bias + residual; remap for coalesced NCHW stores
    int tok2 = tid & 31, cg2 = tid >> 5, cp = cg2 * 8;
    float fin[8];
#pragma unroll
    for (int j = 0; j < 8; j++) fin[j] = 0.f;
    const float* orow = o_s + tok2 * 65;
#pragma unroll 4
    for (int c = 0; c < 64; c++) {
        float oc = orow[c];
        const float* wol = wo_s + c * 65 + cp;
#pragma unroll
        for (int j = 0; j < 8; j++) fin[j] = fmaf(oc, wol[j], fin[j]);
    }
    int b = n0 >> 12;
    int s = (n0 & 4095) + tok2;
#pragma unroll
    for (int j = 0; j < 8; j++) {
        float r = fin[j] + bo[cp + j] + t_s[tok2 * 65 + cp + j];
        out[(b * 64 + cp + j) * 4096 + s] = r;   // lanes = consecutive tokens -> 128B stores
    }
}

// ---------------- launch ----------------
extern "C" void kernel_launch(void* const* d_in, const int* in_sizes, int n_in,
                              void* d_out, int out_size) {
    const float* x  = (const float*)d_in[0];
    const float* w1 = (const float*)d_in[1];
    const float* b1 = (const float*)d_in[2];
    const float* w2 = (const float*)d_in[3];
    const float* b2 = (const float*)d_in[4];
    const float* wq = (const float*)d_in[5];
    const float* wk = (const float*)d_in[6];
    const float* wv = (const float*)d_in[7];
    const float* wo = (const float*)d_in[8];
    const float* bo = (const float*)d_in[9];
    float* out = (float*)d_out;

    cudaFuncSetAttribute(k_attn, cudaFuncAttributeMaxDynamicSharedMemorySize,
                         SMEM_FLOATS * (int)sizeof(float));

    k_transpose_x<<<dim3(128, 2, 2), dim3(32, 8)>>>(x);
    k_transpose_w<<<(2 * 36864 + 255) / 256, 256>>>(w1, w2);
    k_conv<true,  0><<<dim3(8, 32, 2), dim3(256)>>>(b1);
    k_conv<false, 1><<<dim3(8, 32, 2), dim3(256)>>>(b2);
    k_attn<<<256, 256, SMEM_FLOATS * (int)sizeof(float)>>>(wq, wk, wv, wo, bo, out);
}

// round 4
// speedup vs baseline: 1.0195x; 1.0195x over previous
#include <cuda_runtime.h>

// ---------------- scratch (no allocations allowed) ----------------
#define NTOK (2*4096)              // 8192 tokens
__device__ float g_b1[NTOK*64];    // conv1 output (relu), NHWC
__device__ float g_t [NTOK*64];    // conv2 output (= h = t), NHWC
__device__ float g_wt1[64*9*64];   // conv1 weights [ci][k][co]
__device__ float g_wt2[64*9*64];   // conv2 weights [ci][k][co]

__device__ __forceinline__ float ex2f(float x) {
    float y; asm("ex2.approx.f32 %0, %1;" : "=f"(y) : "f"(x)); return y;
}

// ---------------- prep: conv weights [co][ci][3][3] -> [ci][k][co] ----------------
__global__ void k_transpose_w(const float* __restrict__ w1, const float* __restrict__ w2) {
    int i = blockIdx.x * blockDim.x + threadIdx.x;
    if (i >= 2 * 36864) return;
    const float* w = (i < 36864) ? w1 : w2;
    float* dst     = (i < 36864) ? g_wt1 : g_wt2;
    int o  = (i < 36864) ? i : (i - 36864);
    int ci = o / 576;
    int k  = (o % 576) / 64;
    int co = o & 63;
    dst[o] = w[co * 576 + ci * 9 + k];
}

// ---------------- conv3x3, 64->64 channels ----------------
// SRC=0: input = x (NCHW, kernel arg). SRC=1: input = g_b1 (NHWC). output NHWC.
// block: 128 threads = 64 co x 2 row-groups. Each thread: 2 rows x 8 px x 1 co.
// tile: 4 rows x 8 px. grid (8,16,2) = 256 blocks. double-buffered ci chunks of 8.
template<bool RELU, int SRC>
__global__ void __launch_bounds__(128) k_conv(const float* __restrict__ in_x,
                                              const float* __restrict__ bias) {
    const float* __restrict__ wt = (SRC == 0) ? g_wt1 : g_wt2;
    float* __restrict__      out = (SRC == 0) ? g_b1  : g_t;

    __shared__ float w_s[2][4608];       // 8 ci x 9 k x 64 co
    __shared__ float in_s[2][8][72];     // [ci][row*12 + xx], row<6, xx<10 (stride 12)

    const int tid = threadIdx.x;
    const int co  = tid & 63;
    const int rg  = tid >> 6;            // row-group: output rows y0+2rg, y0+2rg+1
    const int x0 = blockIdx.x * 8, y0 = blockIdx.y * 4, b = blockIdx.z;

    float acc0[8], acc1[8];
#pragma unroll
    for (int p = 0; p < 8; p++) { acc0[p] = 0.f; acc1[p] = 0.f; }

    // stage chunk c (ci0 = 8c) into buffer bufi
    auto stage = [&](int c, int bufi) {
        const float4* wsrc = (const float4*)(wt + c * 4608);
        float4* wdst = (float4*)w_s[bufi];
#pragma unroll
        for (int i = 0; i < 9; i++)
            wdst[tid + i * 128] = wsrc[tid + i * 128];
        // inputs: 6 rows x 10 px x 8 ci = 480 elems
#pragma unroll
        for (int e0 = 0; e0 < 512; e0 += 128) {
            int e = e0 + tid;
            if (e < 480) {
                int ci = e & 7;
                int t  = e >> 3;             // 0..59
                int r  = t / 10;
                int xx = t - r * 10;
                int y  = y0 - 1 + r;
                int xg = x0 - 1 + xx;
                float v = 0.f;
                if ((unsigned)y < 64u && (unsigned)xg < 64u) {
                    if (SRC == 0)   // x in NCHW
                        v = in_x[((b * 64 + c * 8 + ci) * 64 + y) * 64 + xg];
                    else            // g_b1 in NHWC
                        v = in_x[((b * 64 + y) * 64 + xg) * 64 + c * 8 + ci];
                }
                in_s[bufi][ci][r * 12 + xx] = v;
            }
        }
    };

    stage(0, 0);
    __syncthreads();

#pragma unroll
    for (int c = 0; c < 8; c++) {
        const int bufi = c & 1;
        if (c < 7) stage(c + 1, bufi ^ 1);

        const float* wb = w_s[bufi];
        const float* ib = &in_s[bufi][0][0];
#pragma unroll
        for (int ci = 0; ci < 8; ci++) {
            const float* wrow = wb + ci * 576 + co;
            float w[9];
#pragma unroll
            for (int k = 0; k < 9; k++) w[k] = wrow[k * 64];

            // 4 input rows for this thread's 2 output rows
            const float* rbase = ib + ci * 72 + rg * 24;
            float A[4][10];
#pragma unroll
            for (int r = 0; r < 4; r++) {
                float4 v0 = *(const float4*)(rbase + r * 12);
                float4 v1 = *(const float4*)(rbase + r * 12 + 4);
                float2 v2 = *(const float2*)(rbase + r * 12 + 8);
                A[r][0]=v0.x; A[r][1]=v0.y; A[r][2]=v0.z; A[r][3]=v0.w;
                A[r][4]=v1.x; A[r][5]=v1.y; A[r][6]=v1.z; A[r][7]=v1.w;
                A[r][8]=v2.x; A[r][9]=v2.y;
            }
#pragma unroll
            for (int p = 0; p < 8; p++) {
                float s0 = acc0[p], s1 = acc1[p];
#pragma unroll
                for (int dy = 0; dy < 3; dy++) {
#pragma unroll
                    for (int dx = 0; dx < 3; dx++) {
                        float wv = w[dy * 3 + dx];
                        s0 = fmaf(wv, A[dy    ][p + dx], s0);
                        s1 = fmaf(wv, A[dy + 1][p + dx], s1);
                    }
                }
                acc0[p] = s0; acc1[p] = s1;
            }
        }
        __syncthreads();
    }

    float bv = bias[co];
    int y = y0 + rg * 2;
    int base0 = ((b * 64 + y    ) * 64 + x0) * 64 + co;
    int base1 = ((b * 64 + y + 1) * 64 + x0) * 64 + co;
#pragma unroll
    for (int p = 0; p < 8; p++) {
        float o0 = acc0[p] + bv, o1 = acc1[p] + bv;
        if (RELU) { o0 = fmaxf(o0, 0.f); o1 = fmaxf(o1, 0.f); }
        out[base0 + p * 64] = o0;        // lanes = co -> coalesced
        out[base1 + p * 64] = o1;
    }
}

// ---------------- attention: 32 tokens per block, 256 threads ----------------
// out_c = sum_d exp(q_c k_d) v_d / sum_d exp(q_c k_d);  final = Wo out + bo + t
#define SMEM_FLOATS (4*4160 + 4*2080)   // 24960 floats = 99840 bytes
__global__ void __launch_bounds__(256) k_attn(
    const float* __restrict__ wq, const float* __restrict__ wk,
    const float* __restrict__ wv, const float* __restrict__ wo,
    const float* __restrict__ bo, float* __restrict__ out)
{
    extern __shared__ float sm[];
    float* wq_s = sm;                  // [l][c], row pad 65
    float* wk_s = sm + 4160;
    float* wv_s = sm + 8320;
    float* wo_s = sm + 12480;          // [c][c'], row pad 65
    float* t_s  = sm + 16640;          // [32][65]
    float* k_s  = t_s + 2080;
    float* v_s  = k_s + 2080;
    float* o_s  = v_s + 2080;

    int tid = threadIdx.x;
    int n0  = blockIdx.x * 32;

    // weights: read coalesced [c][l], write transposed (pad-65 kills bank conflicts)
#pragma unroll 4
    for (int i = 0; i < 16; i++) {
        int g = tid + i * 256;
        int c = g >> 6, l = g & 63;
        wq_s[l * 65 + c] = wq[g];
        wk_s[l * 65 + c] = wk[g];
        wv_s[l * 65 + c] = wv[g];
        wo_s[l * 65 + c] = wo[g];
    }
#pragma unroll
    for (int i = 0; i < 8; i++) {
        int g = tid + i * 256;
        t_s[(g >> 6) * 65 + (g & 63)] = g_t[n0 * 64 + g];
    }
    __syncthreads();

    // phase 1: q/k/v matvecs. thread = (token tt, 8-channel group c0)
    int tt = tid >> 3, cg = tid & 7, c0 = cg * 8;
    float q[8], kk[8], vv[8];
#pragma unroll
    for (int j = 0; j < 8; j++) { q[j] = 0.f; kk[j] = 0.f; vv[j] = 0.f; }
    const float* trow = t_s + tt * 65;
#pragma unroll 4
    for (int l = 0; l < 64; l++) {
        float tl = trow[l];
        const float* wql = wq_s + l * 65 + c0;
        const float* wkl = wk_s + l * 65 + c0;
        const float* wvl = wv_s + l * 65 + c0;
#pragma unroll
        for (int j = 0; j < 8; j++) {
            q[j]  = fmaf(tl, wql[j], q[j]);
            kk[j] = fmaf(tl, wkl[j], kk[j]);
            vv[j] = fmaf(tl, wvl[j], vv[j]);
        }
    }
    // L2 norms over the 8-lane token group
    float sq = 0.f, sk = 0.f;
#pragma unroll
    for (int j = 0; j < 8; j++) { sq = fmaf(q[j], q[j], sq); sk = fmaf(kk[j], kk[j], sk); }
#pragma unroll
    for (int off = 1; off < 8; off <<= 1) {
        sq += __shfl_xor_sync(0xffffffffu, sq, off);
        sk += __shfl_xor_sync(0xffffffffu, sk, off);
    }
    const float LOG2E = 1.4426950408889634f;
    float invq = LOG2E / fmaxf(sqrtf(sq), 1e-12f);   // fold log2(e) into q
    float invk = 1.0f  / fmaxf(sqrtf(sk), 1e-12f);
#pragma unroll
    for (int j = 0; j < 8; j++) {
        q[j] *= invq;
        k_s[tt * 65 + c0 + j] = kk[j] * invk;
        v_s[tt * 65 + c0 + j] = vv[j];
    }
    __syncthreads();

    // phase 2: rank-1 softmax-attention, 2^(qs_c * k_d)
    float num[8], den[8];
#pragma unroll
    for (int j = 0; j < 8; j++) { num[j] = 0.f; den[j] = 0.f; }
    const float* krow = k_s + tt * 65;
    const float* vrow = v_s + tt * 65;
#pragma unroll 2
    for (int d = 0; d < 64; d++) {
        float kd = krow[d];
        float vd = vrow[d];
#pragma unroll
        for (int j = 0; j < 8; j++) {
            float e = ex2f(q[j] * kd);
            num[j] = fmaf(e, vd, num[j]);
            den[j] += e;
        }
    }
#pragma unroll
    for (int j = 0; j < 8; j++)
        o_s[tt * 65 + c0 + j] = __fdividef(num[j], den[j]);
    __syncthreads();

    // phase 3: out-projection + bias + residual; remap for coalesced NCHW stores
    int tok2 = tid & 31, cg2 = tid >> 5, cp = cg2 * 8;
    float fin[8];
#pragma unroll
    for (int j = 0; j < 8; j++) fin[j] = 0.f;
    const float* orow = o_s + tok2 * 65;
#pragma unroll 4
    for (int c = 0; c < 64; c++) {
        float oc = orow[c];
        const float* wol = wo_s + c * 65 + cp;
#pragma unroll
        for (int j = 0; j < 8; j++) fin[j] = fmaf(oc, wol[j], fin[j]);
    }
    int b = n0 >> 12;
    int s = (n0 & 4095) + tok2;
#pragma unroll
    for (int j = 0; j < 8; j++) {
        float r = fin[j] + bo[cp + j] + t_s[tok2 * 65 + cp + j];
        out[(b * 64 + cp + j) * 4096 + s] = r;   // lanes = consecutive tokens -> 128B stores
    }
}

// ---------------- launch ----------------
extern "C" void kernel_launch(void* const* d_in, const int* in_sizes, int n_in,
                              void* d_out, int out_size) {
    const float* x  = (const float*)d_in[0];
    const float* w1 = (const float*)d_in[1];
    const float* b1 = (const float*)d_in[2];
    const float* w2 = (const float*)d_in[3];
    const float* b2 = (const float*)d_in[4];
    const float* wq = (const float*)d_in[5];
    const float* wk = (const float*)d_in[6];
    const float* wv = (const float*)d_in[7];
    const float* wo = (const float*)d_in[8];
    const float* bo = (const float*)d_in[9];
    float* out = (float*)d_out;

    cudaFuncSetAttribute(k_attn, cudaFuncAttributeMaxDynamicSharedMemorySize,
                         SMEM_FLOATS * (int)sizeof(float));

    float* g_b1_p = nullptr;
    cudaGetSymbolAddress((void**)&g_b1_p, g_b1);

    k_transpose_w<<<(2 * 36864 + 255) / 256, 256>>>(w1, w2);
    k_conv<true,  0><<<dim3(8, 16, 2), dim3(128)>>>(x, b1);
    k_conv<false, 1><<<dim3(8, 16, 2), dim3(128)>>>(g_b1_p, b2);
    k_attn<<<256, 256, SMEM_FLOATS * (int)sizeof(float)>>>(wq, wk, wv, wo, bo, out);
}

// round 5
// speedup vs baseline: 1.3740x; 1.3477x over previous
#include <cuda_runtime.h>

typedef unsigned long long ull;

__device__ __forceinline__ ull pack2(float lo, float hi) {
    ull r; asm("mov.b64 %0, {%1, %2};" : "=l"(r) : "f"(lo), "f"(hi)); return r;
}
__device__ __forceinline__ void unpack2(ull v, float& lo, float& hi) {
    asm("mov.b64 {%0, %1}, %2;" : "=f"(lo), "=f"(hi) : "l"(v));
}
__device__ __forceinline__ void fma2(ull& d, ull a, ull b) {
    asm("fma.rn.f32x2 %0, %1, %2, %0;" : "+l"(d) : "l"(a), "l"(b));
}
__device__ __forceinline__ float ex2f(float x) {
    float y; asm("ex2.approx.f32 %0, %1;" : "=f"(y) : "f"(x)); return y;
}

// ---------------- scratch (no allocations allowed) ----------------
#define NTOK (2*4096)              // 8192 tokens
__device__ float g_xt[NTOK*64];    // x in NHWC
__device__ float g_b1[NTOK*64];    // conv1 output (relu), NHWC
__device__ float g_t [NTOK*64];    // conv2 output (= h = t), NHWC
__device__ float g_wt1[64*9*64];   // conv1 weights [ci][k][co-pair interleaved]
__device__ float g_wt2[64*9*64];

// ---------------- prep: NCHW -> NHWC transpose of x ----------------
__global__ void k_transpose_x(const float* __restrict__ x) {
    __shared__ float tile[32][33];
    int b  = blockIdx.z;
    int c0 = blockIdx.y * 32;
    int s0 = blockIdx.x * 32;
    int tx = threadIdx.x, ty = threadIdx.y;
#pragma unroll
    for (int i = 0; i < 32; i += 8)
        tile[ty + i][tx] = x[(b*64 + c0 + ty + i) * 4096 + s0 + tx];
    __syncthreads();
#pragma unroll
    for (int i = 0; i < 32; i += 8)
        g_xt[(b*4096 + s0 + ty + i) * 64 + c0 + tx] = tile[tx][ty + i];
}

// ---- prep: [co][ci][3][3] -> [ci][k][(co2,s)] where pair = (co2, co2+32) ----
__global__ void k_transpose_w(const float* __restrict__ w1, const float* __restrict__ w2) {
    int i = blockIdx.x * blockDim.x + threadIdx.x;
    if (i >= 2 * 36864) return;
    const float* w = (i < 36864) ? w1 : w2;
    float* dst     = (i < 36864) ? g_wt1 : g_wt2;
    int o   = (i < 36864) ? i : (i - 36864);
    int ci  = o / 576;
    int rem = o - ci * 576;
    int kk  = rem >> 6;
    int qq  = rem & 63;
    int co2 = qq >> 1;
    int s   = qq & 1;
    dst[o] = w[(s * 32 + co2) * 576 + ci * 9 + kk];
}

// ---------------- conv3x3 (NHWC in/out), 64->64 channels, f32x2 packed ----------------
// 256 threads = 32 co-pairs x 8 groups (r_o 0..1, h 0..3). thread: 4 px x (co,co+32).
// tile: 2 rows x 16 px x 64 co. grid (4,32,2)=256. double-buffered ci chunks of 8.
template<bool RELU, int SRC>
__global__ void __launch_bounds__(256) k_conv(const float* __restrict__ bias) {
    const float* __restrict__ in  = (SRC == 0) ? g_xt  : g_b1;
    const float* __restrict__ wt  = (SRC == 0) ? g_wt1 : g_wt2;
    float* __restrict__       out = (SRC == 0) ? g_b1  : g_t;

    __shared__ float  w_s[2][4608];      // 8 ci x 9 k x 64 (pair-interleaved)
    __shared__ float2 in_s[2][8][82];    // dup pairs: [ci][r*20 + xx], r<4, xx<18 (+pad)

    const int tid = threadIdx.x;
    const int co2 = tid & 31;
    const int g   = tid >> 5;            // 0..7
    const int r_o = g >> 2;              // output row (0..1)
    const int h   = g & 3;               // 4-px quarter (0..3)
    const int x0 = blockIdx.x * 16, y0 = blockIdx.y * 2, b = blockIdx.z;

    ull acc2[4] = {0ull, 0ull, 0ull, 0ull};

    auto stage = [&](int c, int bufi) {
        const float2* wsrc = (const float2*)(wt + c * 4608);
        float2* wdst = (float2*)w_s[bufi];
#pragma unroll
        for (int i = 0; i < 9; i++)
            wdst[tid + i * 256] = wsrc[tid + i * 256];
        // inputs: 4 rows x 18 px x 8 ci = 576 elems, stored as dup pairs
#pragma unroll
        for (int e0 = 0; e0 < 768; e0 += 256) {
            int e = e0 + tid;
            if (e < 576) {
                int ci = e & 7;
                int t  = e >> 3;             // 0..71
                int r  = t / 18;
                int xx = t - r * 18;
                int y  = y0 - 1 + r;
                int xg = x0 - 1 + xx;
                float v = 0.f;
                if ((unsigned)y < 64u && (unsigned)xg < 64u)
                    v = in[((b * 64 + y) * 64 + xg) * 64 + c * 8 + ci];
                in_s[bufi][ci][r * 20 + xx] = make_float2(v, v);
            }
        }
    };

    stage(0, 0);
    __syncthreads();

#pragma unroll
    for (int c = 0; c < 8; c++) {
        const int bufi = c & 1;
        if (c < 7) stage(c + 1, bufi ^ 1);

#pragma unroll
        for (int ci = 0; ci < 8; ci++) {
            const ull* wp = (const ull*)(w_s[bufi] + ci * 576 + co2 * 2);
            ull w2[9];
#pragma unroll
            for (int k = 0; k < 9; k++) w2[k] = wp[k * 32];
#pragma unroll
            for (int dy = 0; dy < 3; dy++) {
                const ull* arow = (const ull*)&in_s[bufi][ci][(r_o + dy) * 20 + h * 4];
                ull a2[6];
#pragma unroll
                for (int idx = 0; idx < 6; idx++) a2[idx] = arow[idx];
#pragma unroll
                for (int p = 0; p < 4; p++) {
                    fma2(acc2[p], w2[dy*3+0], a2[p]);
                    fma2(acc2[p], w2[dy*3+1], a2[p+1]);
                    fma2(acc2[p], w2[dy*3+2], a2[p+2]);
                }
            }
        }
        __syncthreads();
    }

    float b_lo = bias[co2], b_hi = bias[co2 + 32];
    int y = y0 + r_o;
    int base = ((b * 64 + y) * 64 + x0 + h * 4) * 64;
#pragma unroll
    for (int p = 0; p < 4; p++) {
        float o0, o1;
        unpack2(acc2[p], o0, o1);
        o0 += b_lo; o1 += b_hi;
        if (RELU) { o0 = fmaxf(o0, 0.f); o1 = fmaxf(o1, 0.f); }
        out[base + p * 64 + co2]      = o0;   // lanes = co2 -> coalesced
        out[base + p * 64 + co2 + 32] = o1;
    }
}

// ---------------- attention: 32 tokens/block, 256 threads ----------------
// mapping: tt = tid & 31 (token), cg = tid >> 5 (channel group) -> weight reads broadcast
#define W_STRIDE 66
#define T_STRIDE 65
#define OFF_WQ 0
#define OFF_WK (64*W_STRIDE)
#define OFF_WV (2*64*W_STRIDE)
#define OFF_WO (3*64*W_STRIDE)
#define OFF_T  (4*64*W_STRIDE)
#define OFF_K  (OFF_T + 32*T_STRIDE)
#define OFF_V  (OFF_K + 32*T_STRIDE)
#define OFF_O  (OFF_V + 32*T_STRIDE)
#define OFF_SQ (OFF_O + 32*T_STRIDE)
#define OFF_SK (OFF_SQ + 8*33)
#define SMEM_FLOATS (OFF_SK + 8*33)

__global__ void __launch_bounds__(256) k_attn(
    const float* __restrict__ wq, const float* __restrict__ wk,
    const float* __restrict__ wv, const float* __restrict__ wo,
    const float* __restrict__ bo, float* __restrict__ out)
{
    extern __shared__ float sm[];
    float* wq_s = sm + OFF_WQ;   // [l][c], stride 66 (even -> aligned LDS.64 pairs)
    float* wk_s = sm + OFF_WK;
    float* wv_s = sm + OFF_WV;
    float* wo_s = sm + OFF_WO;   // [c][c'], stride 66
    float* t_s  = sm + OFF_T;    // [32][65]
    float* k_s  = sm + OFF_K;
    float* v_s  = sm + OFF_V;
    float* o_s  = sm + OFF_O;
    float* sq_s = sm + OFF_SQ;   // [8][33]
    float* sk_s = sm + OFF_SK;

    int tid = threadIdx.x;
    int n0  = blockIdx.x * 32;

    // load weights transposed: wX_s[l][c] = wX[c][l]
#pragma unroll 4
    for (int i = 0; i < 16; i++) {
        int gg = tid + i * 256;
        int c = gg >> 6, l = gg & 63;
        wq_s[l * W_STRIDE + c] = wq[gg];
        wk_s[l * W_STRIDE + c] = wk[gg];
        wv_s[l * W_STRIDE + c] = wv[gg];
        wo_s[l * W_STRIDE + c] = wo[gg];
    }
#pragma unroll
    for (int i = 0; i < 8; i++) {
        int gg = tid + i * 256;
        t_s[(gg >> 6) * T_STRIDE + (gg & 63)] = g_t[n0 * 64 + gg];
    }
    __syncthreads();

    const int tt = tid & 31;       // token
    const int cg = tid >> 5;       // channel group (uniform per warp)
    const int c0 = cg * 8;

    // phase 1: q/k/v matvecs, packed. weight reads broadcast across warp.
    ull q2[4], k2[4], v2[4];
#pragma unroll
    for (int j = 0; j < 4; j++) { q2[j] = 0ull; k2[j] = 0ull; v2[j] = 0ull; }
    const float* trow = t_s + tt * T_STRIDE;
#pragma unroll 4
    for (int l = 0; l < 64; l++) {
        float tl = trow[l];
        ull tl2 = pack2(tl, tl);
        const ull* wql = (const ull*)(wq_s + l * W_STRIDE + c0);
        const ull* wkl = (const ull*)(wk_s + l * W_STRIDE + c0);
        const ull* wvl = (const ull*)(wv_s + l * W_STRIDE + c0);
#pragma unroll
        for (int j = 0; j < 4; j++) {
            fma2(q2[j], tl2, wql[j]);
            fma2(k2[j], tl2, wkl[j]);
            fma2(v2[j], tl2, wvl[j]);
        }
    }
    float q[8], kk[8], vv[8];
#pragma unroll
    for (int j = 0; j < 4; j++) {
        unpack2(q2[j], q[2*j], q[2*j+1]);
        unpack2(k2[j], kk[2*j], kk[2*j+1]);
        unpack2(v2[j], vv[2*j], vv[2*j+1]);
    }
    // partial norms -> smem (channel groups live in different warps)
    float sq = 0.f, sk = 0.f;
#pragma unroll
    for (int j = 0; j < 8; j++) { sq = fmaf(q[j], q[j], sq); sk = fmaf(kk[j], kk[j], sk); }
    sq_s[cg * 33 + tt] = sq;
    sk_s[cg * 33 + tt] = sk;
    __syncthreads();
    sq = 0.f; sk = 0.f;
#pragma unroll
    for (int m = 0; m < 8; m++) { sq += sq_s[m * 33 + tt]; sk += sk_s[m * 33 + tt]; }
    const float LOG2E = 1.4426950408889634f;
    float invq = LOG2E / fmaxf(sqrtf(sq), 1e-12f);   // fold log2(e) into q
    float invk = 1.0f  / fmaxf(sqrtf(sk), 1e-12f);
#pragma unroll
    for (int j = 0; j < 8; j++) {
        q[j] *= invq;
        k_s[tt * T_STRIDE + c0 + j] = kk[j] * invk;
        v_s[tt * T_STRIDE + c0 + j] = vv[j];
    }
    __syncthreads();

    // phase 2: rank-1 softmax attention: 2^(qs_c * k_d)
    float num[8], den[8];
#pragma unroll
    for (int j = 0; j < 8; j++) { num[j] = 0.f; den[j] = 0.f; }
    const float* krow = k_s + tt * T_STRIDE;
    const float* vrow = v_s + tt * T_STRIDE;
#pragma unroll 2
    for (int d = 0; d < 64; d++) {
        float kd = krow[d];
        float vd = vrow[d];
#pragma unroll
        for (int j = 0; j < 8; j++) {
            float e = ex2f(q[j] * kd);
            num[j] = fmaf(e, vd, num[j]);
            den[j] += e;
        }
    }
#pragma unroll
    for (int j = 0; j < 8; j++)
        o_s[tt * T_STRIDE + c0 + j] = __fdividef(num[j], den[j]);
    __syncthreads();

    // phase 3: out-projection (packed) + bias + residual; coalesced NCHW stores
    ull fin2[4];
#pragma unroll
    for (int j = 0; j < 4; j++) fin2[j] = 0ull;
    const float* orow = o_s + tt * T_STRIDE;
#pragma unroll 4
    for (int c = 0; c < 64; c++) {
        float oc = orow[c];
        ull oc2 = pack2(oc, oc);
        const ull* wol = (const ull*)(wo_s + c * W_STRIDE + c0);
#pragma unroll
        for (int j = 0; j < 4; j++) fma2(fin2[j], oc2, wol[j]);
    }
    int b = n0 >> 12;
    int s = (n0 & 4095) + tt;
#pragma unroll
    for (int j = 0; j < 4; j++) {
        float f0, f1;
        unpack2(fin2[j], f0, f1);
        int ch = c0 + 2 * j;
        f0 += bo[ch]     + t_s[tt * T_STRIDE + ch];
        f1 += bo[ch + 1] + t_s[tt * T_STRIDE + ch + 1];
        out[(b * 64 + ch    ) * 4096 + s] = f0;   // lanes = consecutive tokens
        out[(b * 64 + ch + 1) * 4096 + s] = f1;
    }
}

// ---------------- launch ----------------
extern "C" void kernel_launch(void* const* d_in, const int* in_sizes, int n_in,
                              void* d_out, int out_size) {
    const float* x  = (const float*)d_in[0];
    const float* w1 = (const float*)d_in[1];
    const float* b1 = (const float*)d_in[2];
    const float* w2 = (const float*)d_in[3];
    const float* b2 = (const float*)d_in[4];
    const float* wq = (const float*)d_in[5];
    const float* wk = (const float*)d_in[6];
    const float* wv = (const float*)d_in[7];
    const float* wo = (const float*)d_in[8];
    const float* bo = (const float*)d_in[9];
    float* out = (float*)d_out;

    cudaFuncSetAttribute(k_attn, cudaFuncAttributeMaxDynamicSharedMemorySize,
                         SMEM_FLOATS * (int)sizeof(float));

    k_transpose_x<<<dim3(128, 2, 2), dim3(32, 8)>>>(x);
    k_transpose_w<<<(2 * 36864 + 255) / 256, 256>>>(w1, w2);
    k_conv<true,  0><<<dim3(4, 32, 2), dim3(256)>>>(b1);
    k_conv<false, 1><<<dim3(4, 32, 2), dim3(256)>>>(b2);
    k_attn<<<256, 256, SMEM_FLOATS * (int)sizeof(float)>>>(wq, wk, wv, wo, bo, out);
}

// round 6
// speedup vs baseline: 1.6607x; 1.2086x over previous
#include <cuda_runtime.h>

typedef unsigned long long ull;

__device__ __forceinline__ ull pack2(float lo, float hi) {
    ull r; asm("mov.b64 %0, {%1, %2};" : "=l"(r) : "f"(lo), "f"(hi)); return r;
}
__device__ __forceinline__ void unpack2(ull v, float& lo, float& hi) {
    asm("mov.b64 {%0, %1}, %2;" : "=f"(lo), "=f"(hi) : "l"(v));
}
__device__ __forceinline__ void fma2(ull& d, ull a, ull b) {
    asm("fma.rn.f32x2 %0, %1, %2, %0;" : "+l"(d) : "l"(a), "l"(b));
}
__device__ __forceinline__ float ex2f(float x) {
    float y; asm("ex2.approx.f32 %0, %1;" : "=f"(y) : "f"(x)); return y;
}

// ---------------- scratch (no allocations allowed) ----------------
#define NTOK (2*4096)              // 8192 tokens
__device__ float g_xt[NTOK*64];    // x in NHWC
__device__ float g_b1[NTOK*64];    // conv1 output (relu), NHWC
__device__ float g_t [NTOK*64];    // conv2 output (= h = t), NHWC
__device__ float g_wt1[64*9*64];   // conv1 weights [ci][k][(co2 pair interleaved)]
__device__ float g_wt2[64*9*64];

// ---------------- prep: NCHW -> NHWC transpose of x ----------------
__global__ void k_transpose_x(const float* __restrict__ x) {
    __shared__ float tile[32][33];
    int b  = blockIdx.z;
    int c0 = blockIdx.y * 32;
    int s0 = blockIdx.x * 32;
    int tx = threadIdx.x, ty = threadIdx.y;
#pragma unroll
    for (int i = 0; i < 32; i += 8)
        tile[ty + i][tx] = x[(b*64 + c0 + ty + i) * 4096 + s0 + tx];
    __syncthreads();
#pragma unroll
    for (int i = 0; i < 32; i += 8)
        g_xt[(b*4096 + s0 + ty + i) * 64 + c0 + tx] = tile[tx][ty + i];
}

// ---- prep: [co][ci][3][3] -> [ci][k][(co2,s)] where pair = (co2, co2+32) ----
__global__ void k_transpose_w(const float* __restrict__ w1, const float* __restrict__ w2) {
    int i = blockIdx.x * blockDim.x + threadIdx.x;
    if (i >= 2 * 36864) return;
    const float* w = (i < 36864) ? w1 : w2;
    float* dst     = (i < 36864) ? g_wt1 : g_wt2;
    int o   = (i < 36864) ? i : (i - 36864);
    int ci  = o / 576;
    int rem = o - ci * 576;
    int kk  = rem >> 6;
    int qq  = rem & 63;
    int co2 = qq >> 1;
    int s   = qq & 1;
    dst[o] = w[(s * 32 + co2) * 576 + ci * 9 + kk];
}

// ---------------- conv3x3 (NHWC in/out), 64->64 channels, f32x2 packed ----------------
// 128 threads = 32 co-pairs x 4 px-quarters. thread: 2 rows x 4 px x (co,co+32).
// tile: 2 rows x 16 px x 64 co. grid (4,32,2)=256. double-buffered ci chunks of 8.
// inputs stored UN-duplicated (broadcast LDS.128/LDS.64 reads + ALU packs).
#define IN_CI_STRIDE 84   // 4 rows * 20 + pad; 84%32bank pattern conflict-free, 16B aligned
template<bool RELU, int SRC>
__global__ void __launch_bounds__(128) k_conv(const float* __restrict__ bias) {
    const float* __restrict__ in  = (SRC == 0) ? g_xt  : g_b1;
    const float* __restrict__ wt  = (SRC == 0) ? g_wt1 : g_wt2;
    float* __restrict__       out = (SRC == 0) ? g_b1  : g_t;

    __shared__ float w_s[2][4608];                // 8 ci x 9 k x 64 (pair-interleaved)
    __shared__ float in_s[2][8 * IN_CI_STRIDE];   // [ci][row*20 + xx], row<4, xx<18

    const int tid = threadIdx.x;
    const int co2 = tid & 31;
    const int h   = tid >> 5;            // px quarter 0..3
    const int x0 = blockIdx.x * 16, y0 = blockIdx.y * 2, b = blockIdx.z;

    ull accA[4] = {0,0,0,0};             // row y0
    ull accB[4] = {0,0,0,0};             // row y0+1

    auto stage = [&](int c, int bufi) {
        const float4* wsrc = (const float4*)(wt + c * 4608);
        float4* wdst = (float4*)w_s[bufi];
#pragma unroll
        for (int i = 0; i < 9; i++)
            wdst[tid + i * 128] = wsrc[tid + i * 128];
        // inputs: 4 rows x 18 px x 8 ci = 576 elems
#pragma unroll
        for (int e0 = 0; e0 < 640; e0 += 128) {
            int e = e0 + tid;
            if (e < 576) {
                int ci = e & 7;
                int t  = e >> 3;             // 0..71
                int r  = t / 18;
                int xx = t - r * 18;
                int y  = y0 - 1 + r;
                int xg = x0 - 1 + xx;
                float v = 0.f;
                if ((unsigned)y < 64u && (unsigned)xg < 64u)
                    v = in[((b * 64 + y) * 64 + xg) * 64 + c * 8 + ci];
                in_s[bufi][ci * IN_CI_STRIDE + r * 20 + xx] = v;
            }
        }
    };

    stage(0, 0);
    __syncthreads();

#pragma unroll
    for (int c = 0; c < 8; c++) {
        const int bufi = c & 1;
        if (c < 7) stage(c + 1, bufi ^ 1);

#pragma unroll
        for (int ci = 0; ci < 8; ci++) {
            const ull* wp = (const ull*)(w_s[bufi] + ci * 576 + co2 * 2);
            ull w2[9];
#pragma unroll
            for (int k = 0; k < 9; k++) w2[k] = wp[k * 32];

            const float* ibase = in_s[bufi] + ci * IN_CI_STRIDE + h * 4;
#pragma unroll
            for (int irow = 0; irow < 4; irow++) {
                float4 v0 = *(const float4*)(ibase + irow * 20);       // broadcast
                float2 v1 = *(const float2*)(ibase + irow * 20 + 4);   // broadcast
                ull d[6];
                d[0] = pack2(v0.x, v0.x); d[1] = pack2(v0.y, v0.y);
                d[2] = pack2(v0.z, v0.z); d[3] = pack2(v0.w, v0.w);
                d[4] = pack2(v1.x, v1.x); d[5] = pack2(v1.y, v1.y);
                if (irow < 3) {            // contributes to row A with dy = irow
#pragma unroll
                    for (int p = 0; p < 4; p++) {
                        fma2(accA[p], w2[irow*3+0], d[p]);
                        fma2(accA[p], w2[irow*3+1], d[p+1]);
                        fma2(accA[p], w2[irow*3+2], d[p+2]);
                    }
                }
                if (irow >= 1) {           // contributes to row B with dy = irow-1
#pragma unroll
                    for (int p = 0; p < 4; p++) {
                        fma2(accB[p], w2[(irow-1)*3+0], d[p]);
                        fma2(accB[p], w2[(irow-1)*3+1], d[p+1]);
                        fma2(accB[p], w2[(irow-1)*3+2], d[p+2]);
                    }
                }
            }
        }
        __syncthreads();
    }

    float b_lo = bias[co2], b_hi = bias[co2 + 32];
    int base = ((b * 64 + y0) * 64 + x0 + h * 4) * 64;
#pragma unroll
    for (int p = 0; p < 4; p++) {
        float a0, a1, c0v, c1v;
        unpack2(accA[p], a0, a1);
        unpack2(accB[p], c0v, c1v);
        a0 += b_lo; a1 += b_hi; c0v += b_lo; c1v += b_hi;
        if (RELU) {
            a0 = fmaxf(a0, 0.f); a1 = fmaxf(a1, 0.f);
            c0v = fmaxf(c0v, 0.f); c1v = fmaxf(c1v, 0.f);
        }
        out[base + p * 64 + co2]            = a0;   // row y0
        out[base + p * 64 + co2 + 32]       = a1;
        out[base + 4096 + p * 64 + co2]     = c0v;  // row y0+1
        out[base + 4096 + p * 64 + co2 + 32]= c1v;
    }
}

// ---------------- attention: 32 tokens/block, 256 threads (R5, unchanged) ----------------
#define W_STRIDE 66
#define T_STRIDE 65
#define OFF_WQ 0
#define OFF_WK (64*W_STRIDE)
#define OFF_WV (2*64*W_STRIDE)
#define OFF_WO (3*64*W_STRIDE)
#define OFF_T  (4*64*W_STRIDE)
#define OFF_K  (OFF_T + 32*T_STRIDE)
#define OFF_V  (OFF_K + 32*T_STRIDE)
#define OFF_O  (OFF_V + 32*T_STRIDE)
#define OFF_SQ (OFF_O + 32*T_STRIDE)
#define OFF_SK (OFF_SQ + 8*33)
#define SMEM_FLOATS (OFF_SK + 8*33)

__global__ void __launch_bounds__(256) k_attn(
    const float* __restrict__ wq, const float* __restrict__ wk,
    const float* __restrict__ wv, const float* __restrict__ wo,
    const float* __restrict__ bo, float* __restrict__ out)
{
    extern __shared__ float sm[];
    float* wq_s = sm + OFF_WQ;
    float* wk_s = sm + OFF_WK;
    float* wv_s = sm + OFF_WV;
    float* wo_s = sm + OFF_WO;
    float* t_s  = sm + OFF_T;
    float* k_s  = sm + OFF_K;
    float* v_s  = sm + OFF_V;
    float* o_s  = sm + OFF_O;
    float* sq_s = sm + OFF_SQ;
    float* sk_s = sm + OFF_SK;

    int tid = threadIdx.x;
    int n0  = blockIdx.x * 32;

#pragma unroll 4
    for (int i = 0; i < 16; i++) {
        int gg = tid + i * 256;
        int c = gg >> 6, l = gg & 63;
        wq_s[l * W_STRIDE + c] = wq[gg];
        wk_s[l * W_STRIDE + c] = wk[gg];
        wv_s[l * W_STRIDE + c] = wv[gg];
        wo_s[l * W_STRIDE + c] = wo[gg];
    }
#pragma unroll
    for (int i = 0; i < 8; i++) {
        int gg = tid + i * 256;
        t_s[(gg >> 6) * T_STRIDE + (gg & 63)] = g_t[n0 * 64 + gg];
    }
    __syncthreads();

    const int tt = tid & 31;
    const int cg = tid >> 5;
    const int c0 = cg * 8;

    ull q2[4], k2[4], v2[4];
#pragma unroll
    for (int j = 0; j < 4; j++) { q2[j] = 0ull; k2[j] = 0ull; v2[j] = 0ull; }
    const float* trow = t_s + tt * T_STRIDE;
#pragma unroll 4
    for (int l = 0; l < 64; l++) {
        float tl = trow[l];
        ull tl2 = pack2(tl, tl);
        const ull* wql = (const ull*)(wq_s + l * W_STRIDE + c0);
        const ull* wkl = (const ull*)(wk_s + l * W_STRIDE + c0);
        const ull* wvl = (const ull*)(wv_s + l * W_STRIDE + c0);
#pragma unroll
        for (int j = 0; j < 4; j++) {
            fma2(q2[j], tl2, wql[j]);
            fma2(k2[j], tl2, wkl[j]);
            fma2(v2[j], tl2, wvl[j]);
        }
    }
    float q[8], kk[8], vv[8];
#pragma unroll
    for (int j = 0; j < 4; j++) {
        unpack2(q2[j], q[2*j], q[2*j+1]);
        unpack2(k2[j], kk[2*j], kk[2*j+1]);
        unpack2(v2[j], vv[2*j], vv[2*j+1]);
    }
    float sq = 0.f, sk = 0.f;
#pragma unroll
    for (int j = 0; j < 8; j++) { sq = fmaf(q[j], q[j], sq); sk = fmaf(kk[j], kk[j], sk); }
    sq_s[cg * 33 + tt] = sq;
    sk_s[cg * 33 + tt] = sk;
    __syncthreads();
    sq = 0.f; sk = 0.f;
#pragma unroll
    for (int m = 0; m < 8; m++) { sq += sq_s[m * 33 + tt]; sk += sk_s[m * 33 + tt]; }
    const float LOG2E = 1.4426950408889634f;
    float invq = LOG2E / fmaxf(sqrtf(sq), 1e-12f);
    float invk = 1.0f  / fmaxf(sqrtf(sk), 1e-12f);
#pragma unroll
    for (int j = 0; j < 8; j++) {
        q[j] *= invq;
        k_s[tt * T_STRIDE + c0 + j] = kk[j] * invk;
        v_s[tt * T_STRIDE + c0 + j] = vv[j];
    }
    __syncthreads();

    float num[8], den[8];
#pragma unroll
    for (int j = 0; j < 8; j++) { num[j] = 0.f; den[j] = 0.f; }
    const float* krow = k_s + tt * T_STRIDE;
    const float* vrow = v_s + tt * T_STRIDE;
#pragma unroll 2
    for (int d = 0; d < 64; d++) {
        float kd = krow[d];
        float vd = vrow[d];
#pragma unroll
        for (int j = 0; j < 8; j++) {
            float e = ex2f(q[j] * kd);
            num[j] = fmaf(e, vd, num[j]);
            den[j] += e;
        }
    }
#pragma unroll
    for (int j = 0; j < 8; j++)
        o_s[tt * T_STRIDE + c0 + j] = __fdividef(num[j], den[j]);
    __syncthreads();

    ull fin2[4];
#pragma unroll
    for (int j = 0; j < 4; j++) fin2[j] = 0ull;
    const float* orow = o_s + tt * T_STRIDE;
#pragma unroll 4
    for (int c = 0; c < 64; c++) {
        float oc = orow[c];
        ull oc2 = pack2(oc, oc);
        const ull* wol = (const ull*)(wo_s + c * W_STRIDE + c0);
#pragma unroll
        for (int j = 0; j < 4; j++) fma2(fin2[j], oc2, wol[j]);
    }
    int b = n0 >> 12;
    int s = (n0 & 4095) + tt;
#pragma unroll
    for (int j = 0; j < 4; j++) {
        float f0, f1;
        unpack2(fin2[j], f0, f1);
        int ch = c0 + 2 * j;
        f0 += bo[ch]     + t_s[tt * T_STRIDE + ch];
        f1 += bo[ch + 1] + t_s[tt * T_STRIDE + ch + 1];
        out[(b * 64 + ch    ) * 4096 + s] = f0;
        out[(b * 64 + ch + 1) * 4096 + s] = f1;
    }
}

// ---------------- launch ----------------
extern "C" void kernel_launch(void* const* d_in, const int* in_sizes, int n_in,
                              void* d_out, int out_size) {
    const float* x  = (const float*)d_in[0];
    const float* w1 = (const float*)d_in[1];
    const float* b1 = (const float*)d_in[2];
    const float* w2 = (const float*)d_in[3];
    const float* b2 = (const float*)d_in[4];
    const float* wq = (const float*)d_in[5];
    const float* wk = (const float*)d_in[6];
    const float* wv = (const float*)d_in[7];
    const float* wo = (const float*)d_in[8];
    const float* bo = (const float*)d_in[9];
    float* out = (float*)d_out;

    cudaFuncSetAttribute(k_attn, cudaFuncAttributeMaxDynamicSharedMemorySize,
                         SMEM_FLOATS * (int)sizeof(float));

    k_transpose_x<<<dim3(128, 2, 2), dim3(32, 8)>>>(x);
    k_transpose_w<<<(2 * 36864 + 255) / 256, 256>>>(w1, w2);
    k_conv<true,  0><<<dim3(4, 32, 2), dim3(128)>>>(b1);
    k_conv<false, 1><<<dim3(4, 32, 2), dim3(128)>>>(b2);
    k_attn<<<256, 256, SMEM_FLOATS * (int)sizeof(float)>>>(wq, wk, wv, wo, bo, out);
}

// round 7
// speedup vs baseline: 1.7867x; 1.0759x over previous
#include <cuda_runtime.h>

typedef unsigned long long ull;

__device__ __forceinline__ ull pack2(float lo, float hi) {
    ull r; asm("mov.b64 %0, {%1, %2};" : "=l"(r) : "f"(lo), "f"(hi)); return r;
}
__device__ __forceinline__ void unpack2(ull v, float& lo, float& hi) {
    asm("mov.b64 {%0, %1}, %2;" : "=f"(lo), "=f"(hi) : "l"(v));
}
__device__ __forceinline__ void fma2(ull& d, ull a, ull b) {
    asm("fma.rn.f32x2 %0, %1, %2, %0;" : "+l"(d) : "l"(a), "l"(b));
}
__device__ __forceinline__ float ex2f(float x) {
    float y; asm("ex2.approx.f32 %0, %1;" : "=f"(y) : "f"(x)); return y;
}

// ---------------- scratch (no allocations allowed) ----------------
#define NTOK (2*4096)              // 8192 tokens
#define PBUF (NTOK*64)             // 524288 floats per partial buffer
__device__ float g_xt[PBUF];       // x in NHWC
__device__ float g_p[4*PBUF];      // conv1 partials (per ci-quarter), no bias/relu
__device__ float g_q[4*PBUF];      // conv2 partials (per ci-quarter), no bias
__device__ float g_wt1[64*9*64];   // conv1 weights [ci][k][(co2,s) pair-interleaved]
__device__ float g_wt2[64*9*64];

// ---------------- prep: NCHW -> NHWC transpose of x ----------------
__global__ void k_transpose_x(const float* __restrict__ x) {
    __shared__ float tile[32][33];
    int b  = blockIdx.z;
    int c0 = blockIdx.y * 32;
    int s0 = blockIdx.x * 32;
    int tx = threadIdx.x, ty = threadIdx.y;
#pragma unroll
    for (int i = 0; i < 32; i += 8)
        tile[ty + i][tx] = x[(b*64 + c0 + ty + i) * 4096 + s0 + tx];
    __syncthreads();
#pragma unroll
    for (int i = 0; i < 32; i += 8)
        g_xt[(b*4096 + s0 + ty + i) * 64 + c0 + tx] = tile[tx][ty + i];
}

// ---- prep: [co][ci][3][3] -> [ci][k][(co2,s)] where pair = (co2, co2+32) ----
__global__ void k_transpose_w(const float* __restrict__ w1, const float* __restrict__ w2) {
    int i = blockIdx.x * blockDim.x + threadIdx.x;
    if (i >= 2 * 36864) return;
    const float* w = (i < 36864) ? w1 : w2;
    float* dst     = (i < 36864) ? g_wt1 : g_wt2;
    int o   = (i < 36864) ? i : (i - 36864);
    int ci  = o / 576;
    int rem = o - ci * 576;
    int kk  = rem >> 6;
    int qq  = rem & 63;
    int co2 = qq >> 1;
    int s   = qq & 1;
    dst[o] = w[(s * 32 + co2) * 576 + ci * 9 + kk];
}

// ---------------- partial conv3x3: 16 input channels per block ----------------
// 128 threads = 32 co-pairs x 4 px-quarters; thread: 2 rows x 4 px x (co,co+32).
// tile 2 rows x 16 px. grid (4,32,8): z = b*4 + quarter. ALL smem staged once, 1 barrier.
// SRC=0: in = g_xt raw;       out = g_p[quarter]
// SRC=1: in = relu(Σ4 g_p + bias1); out = g_q[quarter]
#define IN_CI_STRIDE 84
template<int SRC>
__global__ void __launch_bounds__(128) k_conv(const float* __restrict__ in_bias) {
    const float* __restrict__ wt = (SRC == 0) ? g_wt1 : g_wt2;

    __shared__ float w_s[16 * 576];              // 16 ci x 9 k x 64 (pair-interleaved)
    __shared__ float in_s[16 * IN_CI_STRIDE];    // [ci16][r*20 + xx], r<4, xx<18

    const int tid = threadIdx.x;
    const int co2 = tid & 31;
    const int h   = tid >> 5;                    // px quarter 0..3
    const int x0 = blockIdx.x * 16, y0 = blockIdx.y * 2;
    const int b  = blockIdx.z >> 2;
    const int quarter = blockIdx.z & 3;

    // ---- stage weights: 16 ci x 576 = 9216 floats = 2304 float4
    {
        const float4* wsrc = (const float4*)(wt + quarter * 16 * 576);
        float4* wdst = (float4*)w_s;
#pragma unroll
        for (int i = 0; i < 18; i++)
            wdst[tid + i * 128] = wsrc[tid + i * 128];
    }
    // ---- stage inputs: 4 rows x 18 px x 16 ci = 1152 elems (9 x 128)
    {
        const int ci16 = tid & 15;               // constant per lane
        float bvin = 0.f;
        if (SRC == 1) bvin = in_bias[quarter * 16 + ci16];
#pragma unroll
        for (int i = 0; i < 9; i++) {
            int t  = i * 8 + (tid >> 4);         // 0..71
            int r  = t / 18;
            int xx = t - r * 18;
            int y  = y0 - 1 + r;
            int xg = x0 - 1 + xx;
            float v = 0.f;
            if ((unsigned)y < 64u && (unsigned)xg < 64u) {
                int idx = ((b * 64 + y) * 64 + xg) * 64 + quarter * 16 + ci16;
                if (SRC == 0) {
                    v = g_xt[idx];
                } else {
                    v = g_p[idx] + g_p[idx + PBUF] + g_p[idx + 2*PBUF] + g_p[idx + 3*PBUF];
                    v = fmaxf(v + bvin, 0.f);
                }
            }
            in_s[ci16 * IN_CI_STRIDE + r * 20 + xx] = v;
        }
    }
    __syncthreads();

    ull accA[4] = {0,0,0,0};                     // row y0
    ull accB[4] = {0,0,0,0};                     // row y0+1

#pragma unroll
    for (int ci = 0; ci < 16; ci++) {
        const ull* wp = (const ull*)(w_s + ci * 576 + co2 * 2);
        ull w2[9];
#pragma unroll
        for (int k = 0; k < 9; k++) w2[k] = wp[k * 32];

        const float* ibase = in_s + ci * IN_CI_STRIDE + h * 4;
#pragma unroll
        for (int irow = 0; irow < 4; irow++) {
            float4 v0 = *(const float4*)(ibase + irow * 20);       // broadcast
            float2 v1 = *(const float2*)(ibase + irow * 20 + 4);   // broadcast
            ull d[6];
            d[0] = pack2(v0.x, v0.x); d[1] = pack2(v0.y, v0.y);
            d[2] = pack2(v0.z, v0.z); d[3] = pack2(v0.w, v0.w);
            d[4] = pack2(v1.x, v1.x); d[5] = pack2(v1.y, v1.y);
            if (irow < 3) {
#pragma unroll
                for (int p = 0; p < 4; p++) {
                    fma2(accA[p], w2[irow*3+0], d[p]);
                    fma2(accA[p], w2[irow*3+1], d[p+1]);
                    fma2(accA[p], w2[irow*3+2], d[p+2]);
                }
            }
            if (irow >= 1) {
#pragma unroll
                for (int p = 0; p < 4; p++) {
                    fma2(accB[p], w2[(irow-1)*3+0], d[p]);
                    fma2(accB[p], w2[(irow-1)*3+1], d[p+1]);
                    fma2(accB[p], w2[(irow-1)*3+2], d[p+2]);
                }
            }
        }
    }

    float* __restrict__ out = ((SRC == 0) ? g_p : g_q) + quarter * PBUF;
    int base = ((b * 64 + y0) * 64 + x0 + h * 4) * 64;
#pragma unroll
    for (int p = 0; p < 4; p++) {
        float a0, a1, b0v, b1v;
        unpack2(accA[p], a0, a1);
        unpack2(accB[p], b0v, b1v);
        out[base + p * 64 + co2]             = a0;   // row y0
        out[base + p * 64 + co2 + 32]        = a1;
        out[base + 4096 + p * 64 + co2]      = b0v;  // row y0+1
        out[base + 4096 + p * 64 + co2 + 32] = b1v;
    }
}

// ---------------- attention: 32 tokens/block, 256 threads ----------------
#define W_STRIDE 66
#define T_STRIDE 65
#define OFF_WQ 0
#define OFF_WK (64*W_STRIDE)
#define OFF_WV (2*64*W_STRIDE)
#define OFF_WO (3*64*W_STRIDE)
#define OFF_T  (4*64*W_STRIDE)
#define OFF_K  (OFF_T + 32*T_STRIDE)
#define OFF_V  (OFF_K + 32*T_STRIDE)
#define OFF_O  (OFF_V + 32*T_STRIDE)
#define OFF_SQ (OFF_O + 32*T_STRIDE)
#define OFF_SK (OFF_SQ + 8*33)
#define SMEM_FLOATS (OFF_SK + 8*33)

__global__ void __launch_bounds__(256) k_attn(
    const float* __restrict__ wq, const float* __restrict__ wk,
    const float* __restrict__ wv, const float* __restrict__ wo,
    const float* __restrict__ bo, const float* __restrict__ b2,
    float* __restrict__ out)
{
    extern __shared__ float sm[];
    float* wq_s = sm + OFF_WQ;
    float* wk_s = sm + OFF_WK;
    float* wv_s = sm + OFF_WV;
    float* wo_s = sm + OFF_WO;
    float* t_s  = sm + OFF_T;
    float* k_s  = sm + OFF_K;
    float* v_s  = sm + OFF_V;
    float* o_s  = sm + OFF_O;
    float* sq_s = sm + OFF_SQ;
    float* sk_s = sm + OFF_SK;

    int tid = threadIdx.x;
    int n0  = blockIdx.x * 32;

#pragma unroll 4
    for (int i = 0; i < 16; i++) {
        int gg = tid + i * 256;
        int c = gg >> 6, l = gg & 63;
        wq_s[l * W_STRIDE + c] = wq[gg];
        wk_s[l * W_STRIDE + c] = wk[gg];
        wv_s[l * W_STRIDE + c] = wv[gg];
        wo_s[l * W_STRIDE + c] = wo[gg];
    }
    // t = sum of 4 conv2 partials + bias2
#pragma unroll
    for (int i = 0; i < 8; i++) {
        int gg = tid + i * 256;
        int idx = n0 * 64 + gg;
        float tv = g_q[idx] + g_q[idx + PBUF] + g_q[idx + 2*PBUF] + g_q[idx + 3*PBUF]
                 + b2[gg & 63];
        t_s[(gg >> 6) * T_STRIDE + (gg & 63)] = tv;
    }
    __syncthreads();

    const int tt = tid & 31;
    const int cg = tid >> 5;
    const int c0 = cg * 8;

    ull q2[4], k2[4], v2[4];
#pragma unroll
    for (int j = 0; j < 4; j++) { q2[j] = 0ull; k2[j] = 0ull; v2[j] = 0ull; }
    const float* trow = t_s + tt * T_STRIDE;
#pragma unroll 4
    for (int l = 0; l < 64; l++) {
        float tl = trow[l];
        ull tl2 = pack2(tl, tl);
        const ull* wql = (const ull*)(wq_s + l * W_STRIDE + c0);
        const ull* wkl = (const ull*)(wk_s + l * W_STRIDE + c0);
        const ull* wvl = (const ull*)(wv_s + l * W_STRIDE + c0);
#pragma unroll
        for (int j = 0; j < 4; j++) {
            fma2(q2[j], tl2, wql[j]);
            fma2(k2[j], tl2, wkl[j]);
            fma2(v2[j], tl2, wvl[j]);
        }
    }
    float q[8], kk[8], vv[8];
#pragma unroll
    for (int j = 0; j < 4; j++) {
        unpack2(q2[j], q[2*j], q[2*j+1]);
        unpack2(k2[j], kk[2*j], kk[2*j+1]);
        unpack2(v2[j], vv[2*j], vv[2*j+1]);
    }
    float sq = 0.f, sk = 0.f;
#pragma unroll
    for (int j = 0; j < 8; j++) { sq = fmaf(q[j], q[j], sq); sk = fmaf(kk[j], kk[j], sk); }
    sq_s[cg * 33 + tt] = sq;
    sk_s[cg * 33 + tt] = sk;
    __syncthreads();
    sq = 0.f; sk = 0.f;
#pragma unroll
    for (int m = 0; m < 8; m++) { sq += sq_s[m * 33 + tt]; sk += sk_s[m * 33 + tt]; }
    const float LOG2E = 1.4426950408889634f;
    float invq = LOG2E / fmaxf(sqrtf(sq), 1e-12f);
    float invk = 1.0f  / fmaxf(sqrtf(sk), 1e-12f);
#pragma unroll
    for (int j = 0; j < 8; j++) {
        q[j] *= invq;
        k_s[tt * T_STRIDE + c0 + j] = kk[j] * invk;
        v_s[tt * T_STRIDE + c0 + j] = vv[j];
    }
    __syncthreads();

    float num[8], den[8];
#pragma unroll
    for (int j = 0; j < 8; j++) { num[j] = 0.f; den[j] = 0.f; }
    const float* krow = k_s + tt * T_STRIDE;
    const float* vrow = v_s + tt * T_STRIDE;
#pragma unroll 2
    for (int d = 0; d < 64; d++) {
        float kd = krow[d];
        float vd = vrow[d];
#pragma unroll
        for (int j = 0; j < 8; j++) {
            float e = ex2f(q[j] * kd);
            num[j] = fmaf(e, vd, num[j]);
            den[j] += e;
        }
    }
#pragma unroll
    for (int j = 0; j < 8; j++)
        o_s[tt * T_STRIDE + c0 + j] = __fdividef(num[j], den[j]);
    __syncthreads();

    ull fin2[4];
#pragma unroll
    for (int j = 0; j < 4; j++) fin2[j] = 0ull;
    const float* orow = o_s + tt * T_STRIDE;
#pragma unroll 4
    for (int c = 0; c < 64; c++) {
        float oc = orow[c];
        ull oc2 = pack2(oc, oc);
        const ull* wol = (const ull*)(wo_s + c * W_STRIDE + c0);
#pragma unroll
        for (int j = 0; j < 4; j++) fma2(fin2[j], oc2, wol[j]);
    }
    int b = n0 >> 12;
    int s = (n0 & 4095) + tt;
#pragma unroll
    for (int j = 0; j < 4; j++) {
        float f0, f1;
        unpack2(fin2[j], f0, f1);
        int ch = c0 + 2 * j;
        f0 += bo[ch]     + t_s[tt * T_STRIDE + ch];
        f1 += bo[ch + 1] + t_s[tt * T_STRIDE + ch + 1];
        out[(b * 64 + ch    ) * 4096 + s] = f0;
        out[(b * 64 + ch + 1) * 4096 + s] = f1;
    }
}

// ---------------- launch ----------------
extern "C" void kernel_launch(void* const* d_in, const int* in_sizes, int n_in,
                              void* d_out, int out_size) {
    const float* x  = (const float*)d_in[0];
    const float* w1 = (const float*)d_in[1];
    const float* b1 = (const float*)d_in[2];
    const float* w2 = (const float*)d_in[3];
    const float* b2 = (const float*)d_in[4];
    const float* wq = (const float*)d_in[5];
    const float* wk = (const float*)d_in[6];
    const float* wv = (const float*)d_in[7];
    const float* wo = (const float*)d_in[8];
    const float* bo = (const float*)d_in[9];
    float* out = (float*)d_out;

    cudaFuncSetAttribute(k_attn, cudaFuncAttributeMaxDynamicSharedMemorySize,
                         SMEM_FLOATS * (int)sizeof(float));

    k_transpose_x<<<dim3(128, 2, 2), dim3(32, 8)>>>(x);
    k_transpose_w<<<(2 * 36864 + 255) / 256, 256>>>(w1, w2);
    k_conv<0><<<dim3(4, 32, 8), dim3(128)>>>(nullptr);   // conv1 partials (16 ci each)
    k_conv<1><<<dim3(4, 32, 8), dim3(128)>>>(b1);        // conv2 partials, fused relu(Σ+b1)
    k_attn<<<256, 256, SMEM_FLOATS * (int)sizeof(float)>>>(wq, wk, wv, wo, bo, b2, out);
}